// round 16
// baseline (speedup 1.0000x reference)
#include <cuda_runtime.h>
#include <cuda_fp16.h>
#include <cstdint>

// Shapes: B=4, S=2048, H=D=2048
#define B_ 4
#define S_ 2048
#define H_ 2048
#define M_ (B_ * S_)   // 8192
#define N_ H_
#define K_ H_
#define CH_ (B_ * H_)  // 8192 channels

// WKV chunking
#define NCH 32
#define TCH (S_ / NCH)   // 64

// ---------------- scratch (static device arrays, no allocation) -------------
__device__ __half g_xk[(size_t)M_ * H_];
__device__ __half g_xv[(size_t)M_ * H_];
__device__ __half g_xr[(size_t)M_ * H_];
__device__ __half g_y [(size_t)M_ * H_];
__device__ __half g_wf[4][(size_t)N_ * K_];
__device__ float g_k[(size_t)M_ * H_];
__device__ float g_v[(size_t)M_ * H_];
__device__ float g_r[(size_t)M_ * H_];
__device__ float g_stn[NCH][CH_], g_std[NCH][CH_], g_stm[NCH][CH_];
__device__ float g_pfn[NCH][CH_], g_pfd[NCH][CH_], g_pfm[NCH][CH_];

// ---------------- helpers ----------------
__device__ __forceinline__ uint32_t smem_u32(const void* p) {
    uint32_t a;
    asm("{ .reg .u64 t; cvta.to.shared.u64 t, %1; cvt.u32.u64 %0, t; }"
        : "=r"(a) : "l"(p));
    return a;
}
__device__ __forceinline__ void cpasync16(uint32_t dst, const void* src) {
    asm volatile("cp.async.cg.shared.global [%0], [%1], 16;" :: "r"(dst), "l"(src));
}
__device__ __forceinline__ void cp_commit() {
    asm volatile("cp.async.commit_group;" ::: "memory");
}
template <int N> __device__ __forceinline__ void cp_wait() {
    asm volatile("cp.async.wait_group %0;" :: "n"(N) : "memory");
}
__device__ __forceinline__ void ldsm4(uint32_t* r, uint32_t a) {
    asm volatile("ldmatrix.sync.aligned.m8n8.x4.shared.b16 {%0,%1,%2,%3}, [%4];"
                 : "=r"(r[0]), "=r"(r[1]), "=r"(r[2]), "=r"(r[3]) : "r"(a));
}
__device__ __forceinline__ void mma16816(float* c, const uint32_t* a, const uint32_t* b) {
    asm volatile(
        "mma.sync.aligned.m16n8k16.row.col.f32.f16.f16.f32 "
        "{%0,%1,%2,%3}, {%4,%5,%6,%7}, {%8,%9}, {%0,%1,%2,%3};"
        : "+f"(c[0]), "+f"(c[1]), "+f"(c[2]), "+f"(c[3])
        : "r"(a[0]), "r"(a[1]), "r"(a[2]), "r"(a[3]), "r"(b[0]), "r"(b[1]));
}
__device__ __forceinline__ uint32_t swz(uint32_t off) {   // SW128
    return off ^ ((off >> 3) & 0x70);
}

// ============================================================================
// prep_kernel: mix + conversion of W0/W1; convw23 on stream 2.
// ============================================================================
#define MIX_BLOCKS (M_ * H_ / 4 / 256)        // 16384
#define CONV_BLOCKS_PER_W (N_ * K_ / 4 / 256) // 4096

__global__ __launch_bounds__(256) void prep_kernel(
    const float* __restrict__ hidden,
    const float* __restrict__ tmk, const float* __restrict__ tmv,
    const float* __restrict__ tmr,
    const float* __restrict__ W0, const float* __restrict__ W1) {

    if (blockIdx.x >= MIX_BLOCKS) {
        int blk = blockIdx.x - MIX_BLOCKS;
        int widx = blk / CONV_BLOCKS_PER_W;           // 0 or 1
        int i = (blk % CONV_BLOCKS_PER_W) * 256 + threadIdx.x;
        const float* W = widx ? W1 : W0;
        float4 w = ((const float4*)W)[i];
        __half2* pf = (__half2*)g_wf[widx];
        pf[2 * i]     = __half2(__float2half_rn(w.x), __float2half_rn(w.y));
        pf[2 * i + 1] = __half2(__float2half_rn(w.z), __float2half_rn(w.w));
        return;
    }

    const int H4 = H_ / 4;
    int i = blockIdx.x * 256 + threadIdx.x;
    int h4  = i % H4;
    int row = i / H4;
    int s   = row & (S_ - 1);

    float4 cur = ((const float4*)hidden)[i];
    float4 sh  = make_float4(0.f, 0.f, 0.f, 0.f);
    if (s != 0) sh = ((const float4*)hidden)[i - H4];

    float4 mk = ((const float4*)tmk)[h4];
    float4 mv = ((const float4*)tmv)[h4];
    float4 mr = ((const float4*)tmr)[h4];

    float dx = cur.x - sh.x, dy = cur.y - sh.y, dz = cur.z - sh.z, dw = cur.w - sh.w;

    float vals[3][4];
    vals[0][0] = fmaf(mk.x, dx, sh.x); vals[0][1] = fmaf(mk.y, dy, sh.y);
    vals[0][2] = fmaf(mk.z, dz, sh.z); vals[0][3] = fmaf(mk.w, dw, sh.w);
    vals[1][0] = fmaf(mv.x, dx, sh.x); vals[1][1] = fmaf(mv.y, dy, sh.y);
    vals[1][2] = fmaf(mv.z, dz, sh.z); vals[1][3] = fmaf(mv.w, dw, sh.w);
    vals[2][0] = fmaf(mr.x, dx, sh.x); vals[2][1] = fmaf(mr.y, dy, sh.y);
    vals[2][2] = fmaf(mr.z, dz, sh.z); vals[2][3] = fmaf(mr.w, dw, sh.w);

    __half2* dst[3] = {(__half2*)g_xk, (__half2*)g_xv, (__half2*)g_xr};
#pragma unroll
    for (int t = 0; t < 3; ++t) {
        dst[t][2 * i]     = __half2(__float2half_rn(vals[t][0]), __float2half_rn(vals[t][1]));
        dst[t][2 * i + 1] = __half2(__float2half_rn(vals[t][2]), __float2half_rn(vals[t][3]));
    }
}

__global__ __launch_bounds__(256) void convw23(const float* __restrict__ W2,
                                               const float* __restrict__ W3) {
    int widx = 2 + (int)(blockIdx.x / CONV_BLOCKS_PER_W);
    int i = (blockIdx.x % CONV_BLOCKS_PER_W) * 256 + threadIdx.x;
    const float* W = (widx == 2) ? W2 : W3;
    float4 w = ((const float4*)W)[i];
    __half2* pf = (__half2*)g_wf[widx];
    pf[2 * i]     = __half2(__float2half_rn(w.x), __float2half_rn(w.y));
    pf[2 * i + 1] = __half2(__float2half_rn(w.z), __float2half_rn(w.w));
}

// ============================================================================
// HMMA GEMM core (fp16, K=2048), CTA tile 128x128, 512 threads / 16 warps
// (4x4, warp tile 32x32). BK=128 per stage, stored as TWO 16KB SW128
// sub-blocks per operand. NST=3 (192KB), 1 CTA/SM. 16 stages -> 16 barriers.
// Grid 1024 CTAs/GEMM -> 6.9 waves -> ~1% tail (was 13.5%).
// ============================================================================
#define NST 3
#define BKS 128
#define KBLK 16384                       // 128 rows x 128B, one K-half block
#define STG_A (2 * KBLK)                 // 32KB
#define STG_B (2 * KBLK)                 // 32KB
#define STGB  (STG_A + STG_B)            // 64KB per stage
#define NSTEP (K_ / BKS)                 // 16

__device__ __forceinline__ void gemm_core(
    const __half* __restrict__ A, const __half* __restrict__ Bf,
    float* __restrict__ C, bool sig, char* sm, int bx, int by) {

    const int tid  = threadIdx.x;
    const int wid  = tid >> 5;
    const int lane = tid & 31;
    const int wm   = wid >> 2;      // 0..3 : 32-row strip
    const int wn   = wid & 3;       // 0..3 : 32-col strip
    const int g    = lane >> 2;
    const int t4   = lane & 3;

    const int rowA0 = by * 128;
    const int rowB0 = bx * 128;

    const uint32_t sA0 = smem_u32(sm);

    auto load_stage = [&](int st, int slot) {
        int k0 = st * BKS;
        uint32_t base = sA0 + slot * STGB;
        // A: 4096 16B-chunks? No: 128 rows x 2 kb x 8 chunks = 2048 chunks
#pragma unroll
        for (int i = 0; i < 4; ++i) {
            int id = i * 512 + tid;              // 0..2047
            int kb = id >> 10;                   // K-half
            int rem = id & 1023;
            int row = rem >> 3, c = rem & 7;
            uint32_t sw = swz(row * 128 + c * 16);
            cpasync16(base + kb * KBLK + sw,
                      A + (size_t)(rowA0 + row) * K_ + k0 + kb * 64 + c * 8);
        }
#pragma unroll
        for (int i = 0; i < 4; ++i) {
            int id = i * 512 + tid;
            int kb = id >> 10;
            int rem = id & 1023;
            int row = rem >> 3, c = rem & 7;
            uint32_t sw = swz(row * 128 + c * 16);
            cpasync16(base + STG_A + kb * KBLK + sw,
                      Bf + (size_t)(rowB0 + row) * K_ + k0 + kb * 64 + c * 8);
        }
    };

    const int tsel = lane >> 3;
    const int rin  = lane & 7;
    const int aRowBase = wm * 32 + (tsel & 1) * 8 + rin;
    const int aColBase = (tsel >> 1) * 16;
    const int bRowBase = wn * 32 + (tsel >> 1) * 8 + rin;
    const int bColBase = (tsel & 1) * 16;

    float acc[2][4][4];
#pragma unroll
    for (int i = 0; i < 2; ++i)
#pragma unroll
        for (int j = 0; j < 4; ++j)
#pragma unroll
            for (int r = 0; r < 4; ++r) acc[i][j][r] = 0.f;

    load_stage(0, 0); cp_commit();
    load_stage(1, 1); cp_commit();

    for (int kt = 0; kt < NSTEP; ++kt) {
        const int slot = kt % NST;
        if (kt + 1 < NSTEP) cp_wait<1>(); else cp_wait<0>();
        __syncthreads();

        if (kt + 2 < NSTEP) { load_stage(kt + 2, (kt + 2) % NST); cp_commit(); }

        const uint32_t aBase = sA0 + slot * STGB;
        const uint32_t bBase = aBase + STG_A;

#pragma unroll
        for (int kc = 0; kc < 8; ++kc) {
            const int kb  = kc >> 2;
            const int kcl = kc & 3;
            uint32_t afr[2][4];
#pragma unroll
            for (int mt = 0; mt < 2; ++mt)
                ldsm4(afr[mt], aBase + kb * KBLK +
                               swz((aRowBase + mt * 16) * 128 + kcl * 32 + aColBase));
            uint32_t bfr[2][4];
#pragma unroll
            for (int np = 0; np < 2; ++np)
                ldsm4(bfr[np], bBase + kb * KBLK +
                               swz((bRowBase + np * 16) * 128 + kcl * 32 + bColBase));
#pragma unroll
            for (int mt = 0; mt < 2; ++mt)
#pragma unroll
                for (int nt = 0; nt < 4; ++nt)
                    mma16816(acc[mt][nt], afr[mt], &bfr[nt >> 1][(nt & 1) * 2]);
        }
    }

#pragma unroll
    for (int mt = 0; mt < 2; ++mt) {
        size_t row = (size_t)rowA0 + wm * 32 + mt * 16 + g;
#pragma unroll
        for (int nt = 0; nt < 4; ++nt) {
            int col = rowB0 + wn * 32 + nt * 8 + 2 * t4;
            float2 lo = make_float2(acc[mt][nt][0], acc[mt][nt][1]);
            float2 hi = make_float2(acc[mt][nt][2], acc[mt][nt][3]);
            if (sig) {
                lo.x = 1.f / (1.f + __expf(-lo.x)); lo.y = 1.f / (1.f + __expf(-lo.y));
                hi.x = 1.f / (1.f + __expf(-hi.x)); hi.y = 1.f / (1.f + __expf(-hi.y));
            }
            *(float2*)(C + row * N_ + col) = lo;
            *(float2*)(C + (row + 8) * N_ + col) = hi;
        }
    }
}

__global__ __launch_bounds__(512) void gemm_kv() {
    extern __shared__ char sm[];
    if (blockIdx.z == 0)
        gemm_core(g_xk, g_wf[0], g_k, false, sm, blockIdx.x, blockIdx.y);
    else
        gemm_core(g_xv, g_wf[1], g_v, false, sm, blockIdx.x, blockIdx.y);
}

__global__ __launch_bounds__(512) void gemm_r() {
    extern __shared__ char sm[];
    gemm_core(g_xr, g_wf[2], g_r, true, sm, blockIdx.x, blockIdx.y);
}

__global__ __launch_bounds__(512) void gemm_out(float* __restrict__ out) {
    extern __shared__ char sm[];
    gemm_core(g_y, g_wf[3], out, false, sm, blockIdx.x, blockIdx.y);
}

// ============================================================================
// WKV chunked scan (3 passes) — unchanged.
// ============================================================================
__global__ __launch_bounds__(256) void wkv_pass1(const float* __restrict__ time_decay) {
    const int c = blockIdx.y;
    const int t = blockIdx.x * blockDim.x + threadIdx.x;
    const int b = t >> 11;
    const int d = t & (H_ - 1);
    const float w = -__expf(time_decay[d]);

    float num = 0.f, den = 0.f, mx = -1e38f;
    size_t idx = (size_t)b * S_ * H_ + (size_t)c * TCH * H_ + d;
#pragma unroll 8
    for (int s = 0; s < TCH; ++s, idx += H_) {
        float k = g_k[idx];
        float v = g_v[idx];
        float mw  = mx + w;
        float mn  = fmaxf(mw, k);
        float e1  = __expf(mw - mn);
        float e2  = __expf(k - mn);
        num = e1 * num + e2 * v;
        den = e1 * den + e2;
        mx  = mn;
    }
    g_stn[c][t] = num; g_std[c][t] = den; g_stm[c][t] = mx;
}

__global__ __launch_bounds__(256) void wkv_pass2(const float* __restrict__ time_decay) {
    const int t = blockIdx.x * blockDim.x + threadIdx.x;
    const int d = t & (H_ - 1);
    const float Tw = -__expf(time_decay[d]) * (float)TCH;

    float num = 0.f, den = 0.f, mx = -1e38f;
#pragma unroll
    for (int cb = 0; cb < NCH; cb += 8) {
        float bn[8], bd_[8], bm[8];
#pragma unroll
        for (int j = 0; j < 8; ++j) {
            bn[j]  = g_stn[cb + j][t];
            bd_[j] = g_std[cb + j][t];
            bm[j]  = g_stm[cb + j][t];
        }
#pragma unroll
        for (int j = 0; j < 8; ++j) {
            const int c = cb + j;
            g_pfn[c][t] = num; g_pfd[c][t] = den; g_pfm[c][t] = mx;
            float m1 = mx + Tw;
            float mm = fmaxf(m1, bm[j]);
            float e1 = __expf(m1 - mm);
            float e2 = __expf(bm[j] - mm);
            num = e1 * num + e2 * bn[j];
            den = e1 * den + e2 * bd_[j];
            mx  = mm;
        }
    }
}

__global__ __launch_bounds__(256) void wkv_pass3(const float* __restrict__ time_decay,
                                                 const float* __restrict__ time_first) {
    const int c = blockIdx.y;
    const int t = blockIdx.x * blockDim.x + threadIdx.x;
    const int b = t >> 11;
    const int d = t & (H_ - 1);
    const float w  = -__expf(time_decay[d]);
    const float tf = time_first[d];

    float num = g_pfn[c][t], den = g_pfd[c][t], mx = g_pfm[c][t];
    size_t idx = (size_t)b * S_ * H_ + (size_t)c * TCH * H_ + d;
#pragma unroll 8
    for (int s = 0; s < TCH; ++s, idx += H_) {
        float k = g_k[idx];
        float v = g_v[idx];
        float r = g_r[idx];

        float ktf = k + tf;
        float mo  = fmaxf(mx, ktf);
        float e1  = __expf(mx - mo);
        float e2  = __expf(ktf - mo);
        float out = __fdividef(e1 * num + e2 * v, e1 * den + e2);
        g_y[idx] = __float2half_rn(r * out);

        float mw  = mx + w;
        float mn  = fmaxf(mw, k);
        float e1n = __expf(mw - mn);
        float e2n = __expf(k - mn);
        num = e1n * num + e2n * v;
        den = e1n * den + e2n;
        mx  = mn;
    }
}

// ============================================================================
// Launch: R12/R15 two-stream structure, new gemm tiling (128x128, BK=128).
// ============================================================================
extern "C" void kernel_launch(void* const* d_in, const int* in_sizes, int n_in,
                              void* d_out, int out_size) {
    const float* hidden     = (const float*)d_in[0];
    const float* time_decay = (const float*)d_in[1];
    const float* time_first = (const float*)d_in[2];
    const float* tmk        = (const float*)d_in[3];
    const float* tmv        = (const float*)d_in[4];
    const float* tmr        = (const float*)d_in[5];
    const float* Wk         = (const float*)d_in[6];
    const float* Wv         = (const float*)d_in[7];
    const float* Wr         = (const float*)d_in[8];
    const float* Wo         = (const float*)d_in[9];
    float* out              = (float*)d_out;

    const int shm = NST * STGB;   // 192 KB

    static cudaStream_t s2 = nullptr;
    static cudaEvent_t ePrep = nullptr, eKv = nullptr, eR = nullptr;
    if (s2 == nullptr) {
        cudaFuncSetAttribute(gemm_kv,  cudaFuncAttributeMaxDynamicSharedMemorySize, shm);
        cudaFuncSetAttribute(gemm_r,   cudaFuncAttributeMaxDynamicSharedMemorySize, shm);
        cudaFuncSetAttribute(gemm_out, cudaFuncAttributeMaxDynamicSharedMemorySize, shm);
        cudaStreamCreateWithFlags(&s2, cudaStreamNonBlocking);
        cudaEventCreateWithFlags(&ePrep, cudaEventDisableTiming);
        cudaEventCreateWithFlags(&eKv,   cudaEventDisableTiming);
        cudaEventCreateWithFlags(&eR,    cudaEventDisableTiming);
    }

    // main: prep (mix + W0/W1)
    prep_kernel<<<MIX_BLOCKS + 2 * CONV_BLOCKS_PER_W, 256>>>(
        hidden, tmk, tmv, tmr, Wk, Wv);
    cudaEventRecord(ePrep, 0);

    // s2: convW23 overlapping gemm_kv
    cudaStreamWaitEvent(s2, ePrep, 0);
    convw23<<<2 * CONV_BLOCKS_PER_W, 256, 0, s2>>>(Wr, Wo);

    // main: k,v GEMMs
    dim3 gkv(N_ / 128, M_ / 128, 2);     // (16, 64, 2)
    gemm_kv<<<gkv, 512, shm>>>();
    cudaEventRecord(eKv, 0);

    // s2: r GEMM after kv (overlaps wkv pass1/pass2)
    cudaStreamWaitEvent(s2, eKv, 0);
    dim3 gfull(N_ / 128, M_ / 128);      // (16, 64)
    gemm_r<<<gfull, 512, shm, s2>>>();
    cudaEventRecord(eR, s2);

    // main: wkv pass1 + pass2
    dim3 gp(CH_ / 256, NCH);
    wkv_pass1<<<gp, 256>>>(time_decay);
    wkv_pass2<<<CH_ / 256, 256>>>(time_decay);

    // join: pass3 needs g_r
    cudaStreamWaitEvent(0, eR, 0);
    wkv_pass3<<<gp, 256>>>(time_decay, time_first);

    // main: output GEMM
    gemm_out<<<gfull, 512, shm>>>(out);
}

// round 17
// speedup vs baseline: 1.0811x; 1.0811x over previous
#include <cuda_runtime.h>
#include <cuda_fp16.h>
#include <cstdint>

// Shapes: B=4, S=2048, H=D=2048
#define B_ 4
#define S_ 2048
#define H_ 2048
#define M_ (B_ * S_)   // 8192
#define N_ H_
#define K_ H_
#define CH_ (B_ * H_)  // 8192 channels

// WKV chunking
#define NCH 32
#define TCH (S_ / NCH)   // 64

// ---------------- scratch (static device arrays, no allocation) -------------
__device__ __half g_xk[(size_t)M_ * H_];
__device__ __half g_xv[(size_t)M_ * H_];
__device__ __half g_xr[(size_t)M_ * H_];
__device__ __half g_y [(size_t)M_ * H_];
__device__ __half g_wf[4][(size_t)N_ * K_];
__device__ __half g_k[(size_t)M_ * H_];
__device__ __half g_v[(size_t)M_ * H_];
__device__ __half g_r[(size_t)M_ * H_];
__device__ float g_stn[NCH][CH_], g_std[NCH][CH_], g_stm[NCH][CH_];
__device__ float g_pfn[NCH][CH_], g_pfd[NCH][CH_], g_pfm[NCH][CH_];

// ---------------- helpers ----------------
__device__ __forceinline__ uint32_t smem_u32(const void* p) {
    uint32_t a;
    asm("{ .reg .u64 t; cvta.to.shared.u64 t, %1; cvt.u32.u64 %0, t; }"
        : "=r"(a) : "l"(p));
    return a;
}
__device__ __forceinline__ void cpasync16(uint32_t dst, const void* src) {
    asm volatile("cp.async.cg.shared.global [%0], [%1], 16;" :: "r"(dst), "l"(src));
}
__device__ __forceinline__ void cp_commit() {
    asm volatile("cp.async.commit_group;" ::: "memory");
}
template <int N> __device__ __forceinline__ void cp_wait() {
    asm volatile("cp.async.wait_group %0;" :: "n"(N) : "memory");
}
__device__ __forceinline__ void ldsm4(uint32_t* r, uint32_t a) {
    asm volatile("ldmatrix.sync.aligned.m8n8.x4.shared.b16 {%0,%1,%2,%3}, [%4];"
                 : "=r"(r[0]), "=r"(r[1]), "=r"(r[2]), "=r"(r[3]) : "r"(a));
}
__device__ __forceinline__ void mma16816(float* c, const uint32_t* a, const uint32_t* b) {
    asm volatile(
        "mma.sync.aligned.m16n8k16.row.col.f32.f16.f16.f32 "
        "{%0,%1,%2,%3}, {%4,%5,%6,%7}, {%8,%9}, {%0,%1,%2,%3};"
        : "+f"(c[0]), "+f"(c[1]), "+f"(c[2]), "+f"(c[3])
        : "r"(a[0]), "r"(a[1]), "r"(a[2]), "r"(a[3]), "r"(b[0]), "r"(b[1]));
}
__device__ __forceinline__ uint32_t swz(uint32_t off) {   // SW128
    return off ^ ((off >> 3) & 0x70);
}

// ============================================================================
// prep_kernel: mix + conversion of W0/W1; convw23 on stream 2.
// ============================================================================
#define MIX_BLOCKS (M_ * H_ / 4 / 256)        // 16384
#define CONV_BLOCKS_PER_W (N_ * K_ / 4 / 256) // 4096

__global__ __launch_bounds__(256) void prep_kernel(
    const float* __restrict__ hidden,
    const float* __restrict__ tmk, const float* __restrict__ tmv,
    const float* __restrict__ tmr,
    const float* __restrict__ W0, const float* __restrict__ W1) {

    if (blockIdx.x >= MIX_BLOCKS) {
        int blk = blockIdx.x - MIX_BLOCKS;
        int widx = blk / CONV_BLOCKS_PER_W;           // 0 or 1
        int i = (blk % CONV_BLOCKS_PER_W) * 256 + threadIdx.x;
        const float* W = widx ? W1 : W0;
        float4 w = ((const float4*)W)[i];
        __half2* pf = (__half2*)g_wf[widx];
        pf[2 * i]     = __half2(__float2half_rn(w.x), __float2half_rn(w.y));
        pf[2 * i + 1] = __half2(__float2half_rn(w.z), __float2half_rn(w.w));
        return;
    }

    const int H4 = H_ / 4;
    int i = blockIdx.x * 256 + threadIdx.x;
    int h4  = i % H4;
    int row = i / H4;
    int s   = row & (S_ - 1);

    float4 cur = ((const float4*)hidden)[i];
    float4 sh  = make_float4(0.f, 0.f, 0.f, 0.f);
    if (s != 0) sh = ((const float4*)hidden)[i - H4];

    float4 mk = ((const float4*)tmk)[h4];
    float4 mv = ((const float4*)tmv)[h4];
    float4 mr = ((const float4*)tmr)[h4];

    float dx = cur.x - sh.x, dy = cur.y - sh.y, dz = cur.z - sh.z, dw = cur.w - sh.w;

    float vals[3][4];
    vals[0][0] = fmaf(mk.x, dx, sh.x); vals[0][1] = fmaf(mk.y, dy, sh.y);
    vals[0][2] = fmaf(mk.z, dz, sh.z); vals[0][3] = fmaf(mk.w, dw, sh.w);
    vals[1][0] = fmaf(mv.x, dx, sh.x); vals[1][1] = fmaf(mv.y, dy, sh.y);
    vals[1][2] = fmaf(mv.z, dz, sh.z); vals[1][3] = fmaf(mv.w, dw, sh.w);
    vals[2][0] = fmaf(mr.x, dx, sh.x); vals[2][1] = fmaf(mr.y, dy, sh.y);
    vals[2][2] = fmaf(mr.z, dz, sh.z); vals[2][3] = fmaf(mr.w, dw, sh.w);

    __half2* dst[3] = {(__half2*)g_xk, (__half2*)g_xv, (__half2*)g_xr};
#pragma unroll
    for (int t = 0; t < 3; ++t) {
        dst[t][2 * i]     = __half2(__float2half_rn(vals[t][0]), __float2half_rn(vals[t][1]));
        dst[t][2 * i + 1] = __half2(__float2half_rn(vals[t][2]), __float2half_rn(vals[t][3]));
    }
}

__global__ __launch_bounds__(256) void convw23(const float* __restrict__ W2,
                                               const float* __restrict__ W3) {
    int widx = 2 + (int)(blockIdx.x / CONV_BLOCKS_PER_W);
    int i = (blockIdx.x % CONV_BLOCKS_PER_W) * 256 + threadIdx.x;
    const float* W = (widx == 2) ? W2 : W3;
    float4 w = ((const float4*)W)[i];
    __half2* pf = (__half2*)g_wf[widx];
    pf[2 * i]     = __half2(__float2half_rn(w.x), __float2half_rn(w.y));
    pf[2 * i + 1] = __half2(__float2half_rn(w.z), __float2half_rn(w.w));
}

// ============================================================================
// HMMA GEMM core — EXACT R15 config (best measured): CTA 256x128, 512 thr /
// 16 warps (4x4, warp tile 64x32), BK=64/stage, NST=3 (144KB), SW128.
// Templated epilogue output type: __half (proj GEMMs) or float (out GEMM).
// ============================================================================
#define NST 3
#define BKS 64
#define STG_A (256 * 128)               // 32KB
#define STG_B (128 * 128)               // 16KB
#define STGB  (STG_A + STG_B)           // 48KB per stage
#define NSTEP (K_ / BKS)                // 32

template <typename OutT, bool SIG>
__device__ __forceinline__ void gemm_core(
    const __half* __restrict__ A, const __half* __restrict__ Bf,
    OutT* __restrict__ C, char* sm, int bx, int by) {

    const int tid  = threadIdx.x;
    const int wid  = tid >> 5;
    const int lane = tid & 31;
    const int wm   = wid >> 2;      // 0..3 : 64-row strip
    const int wn   = wid & 3;       // 0..3 : 32-col strip
    const int g    = lane >> 2;
    const int t4   = lane & 3;

    const int rowA0 = by * 256;
    const int rowB0 = bx * 128;

    const uint32_t sA0 = smem_u32(sm);

    auto load_stage = [&](int st, int slot) {
        int k0 = st * BKS;
        uint32_t base = sA0 + slot * STGB;
#pragma unroll
        for (int i = 0; i < 4; ++i) {              // A: 256 rows
            int id = i * 512 + tid;                // 0..2047
            int row = id >> 3, c = id & 7;
            uint32_t sw = swz(row * 128 + c * 16);
            cpasync16(base + sw, A + (size_t)(rowA0 + row) * K_ + k0 + c * 8);
        }
#pragma unroll
        for (int i = 0; i < 2; ++i) {              // B: 128 rows
            int id = i * 512 + tid;                // 0..1023
            int row = id >> 3, c = id & 7;
            uint32_t sw = swz(row * 128 + c * 16);
            cpasync16(base + STG_A + sw, Bf + (size_t)(rowB0 + row) * K_ + k0 + c * 8);
        }
    };

    const int tsel = lane >> 3;
    const int rin  = lane & 7;
    const int aRowBase = wm * 64 + (tsel & 1) * 8 + rin;
    const int aColBase = (tsel >> 1) * 16;
    const int bRowBase = wn * 32 + (tsel >> 1) * 8 + rin;
    const int bColBase = (tsel & 1) * 16;

    float acc[4][4][4];
#pragma unroll
    for (int i = 0; i < 4; ++i)
#pragma unroll
        for (int j = 0; j < 4; ++j)
#pragma unroll
            for (int r = 0; r < 4; ++r) acc[i][j][r] = 0.f;

    load_stage(0, 0); cp_commit();
    load_stage(1, 1); cp_commit();

    for (int kt = 0; kt < NSTEP; ++kt) {
        const int slot = kt % NST;
        if (kt + 1 < NSTEP) cp_wait<1>(); else cp_wait<0>();
        __syncthreads();

        if (kt + 2 < NSTEP) { load_stage(kt + 2, (kt + 2) % NST); cp_commit(); }

        const uint32_t aBase = sA0 + slot * STGB;
        const uint32_t bBase = aBase + STG_A;

#pragma unroll
        for (int kc = 0; kc < 4; ++kc) {
            uint32_t afr[4][4];
#pragma unroll
            for (int mt = 0; mt < 4; ++mt)
                ldsm4(afr[mt], aBase + swz((aRowBase + mt * 16) * 128 + kc * 32 + aColBase));
            uint32_t bfr[2][4];
#pragma unroll
            for (int np = 0; np < 2; ++np)
                ldsm4(bfr[np], bBase + swz((bRowBase + np * 16) * 128 + kc * 32 + bColBase));
#pragma unroll
            for (int mt = 0; mt < 4; ++mt)
#pragma unroll
                for (int nt = 0; nt < 4; ++nt)
                    mma16816(acc[mt][nt], afr[mt], &bfr[nt >> 1][(nt & 1) * 2]);
        }
    }

#pragma unroll
    for (int mt = 0; mt < 4; ++mt) {
        size_t row = (size_t)rowA0 + wm * 64 + mt * 16 + g;
#pragma unroll
        for (int nt = 0; nt < 4; ++nt) {
            int col = rowB0 + wn * 32 + nt * 8 + 2 * t4;
            float2 lo = make_float2(acc[mt][nt][0], acc[mt][nt][1]);
            float2 hi = make_float2(acc[mt][nt][2], acc[mt][nt][3]);
            if (SIG) {
                lo.x = 1.f / (1.f + __expf(-lo.x)); lo.y = 1.f / (1.f + __expf(-lo.y));
                hi.x = 1.f / (1.f + __expf(-hi.x)); hi.y = 1.f / (1.f + __expf(-hi.y));
            }
            if constexpr (sizeof(OutT) == 2) {
                *(__half2*)((__half*)C + row * N_ + col) = __floats2half2_rn(lo.x, lo.y);
                *(__half2*)((__half*)C + (row + 8) * N_ + col) = __floats2half2_rn(hi.x, hi.y);
            } else {
                *(float2*)((float*)C + row * N_ + col) = lo;
                *(float2*)((float*)C + (row + 8) * N_ + col) = hi;
            }
        }
    }
}

__global__ __launch_bounds__(512) void gemm_kv() {
    extern __shared__ char sm[];
    if (blockIdx.z == 0)
        gemm_core<__half, false>(g_xk, g_wf[0], g_k, sm, blockIdx.x, blockIdx.y);
    else
        gemm_core<__half, false>(g_xv, g_wf[1], g_v, sm, blockIdx.x, blockIdx.y);
}

__global__ __launch_bounds__(512) void gemm_r() {
    extern __shared__ char sm[];
    gemm_core<__half, true>(g_xr, g_wf[2], g_r, sm, blockIdx.x, blockIdx.y);
}

__global__ __launch_bounds__(512) void gemm_out(float* __restrict__ out) {
    extern __shared__ char sm[];
    gemm_core<float, false>(g_y, g_wf[3], out, sm, blockIdx.x, blockIdx.y);
}

// ============================================================================
// WKV chunked scan (3 passes) — k,v,r now fp16 in gmem, fp32 in registers.
// ============================================================================
__global__ __launch_bounds__(256) void wkv_pass1(const float* __restrict__ time_decay) {
    const int c = blockIdx.y;
    const int t = blockIdx.x * blockDim.x + threadIdx.x;
    const int b = t >> 11;
    const int d = t & (H_ - 1);
    const float w = -__expf(time_decay[d]);

    float num = 0.f, den = 0.f, mx = -1e38f;
    size_t idx = (size_t)b * S_ * H_ + (size_t)c * TCH * H_ + d;
#pragma unroll 8
    for (int s = 0; s < TCH; ++s, idx += H_) {
        float k = __half2float(g_k[idx]);
        float v = __half2float(g_v[idx]);
        float mw  = mx + w;
        float mn  = fmaxf(mw, k);
        float e1  = __expf(mw - mn);
        float e2  = __expf(k - mn);
        num = e1 * num + e2 * v;
        den = e1 * den + e2;
        mx  = mn;
    }
    g_stn[c][t] = num; g_std[c][t] = den; g_stm[c][t] = mx;
}

__global__ __launch_bounds__(256) void wkv_pass2(const float* __restrict__ time_decay) {
    const int t = blockIdx.x * blockDim.x + threadIdx.x;
    const int d = t & (H_ - 1);
    const float Tw = -__expf(time_decay[d]) * (float)TCH;

    float num = 0.f, den = 0.f, mx = -1e38f;
#pragma unroll
    for (int cb = 0; cb < NCH; cb += 8) {
        float bn[8], bd_[8], bm[8];
#pragma unroll
        for (int j = 0; j < 8; ++j) {
            bn[j]  = g_stn[cb + j][t];
            bd_[j] = g_std[cb + j][t];
            bm[j]  = g_stm[cb + j][t];
        }
#pragma unroll
        for (int j = 0; j < 8; ++j) {
            const int c = cb + j;
            g_pfn[c][t] = num; g_pfd[c][t] = den; g_pfm[c][t] = mx;
            float m1 = mx + Tw;
            float mm = fmaxf(m1, bm[j]);
            float e1 = __expf(m1 - mm);
            float e2 = __expf(bm[j] - mm);
            num = e1 * num + e2 * bn[j];
            den = e1 * den + e2 * bd_[j];
            mx  = mm;
        }
    }
}

__global__ __launch_bounds__(256) void wkv_pass3(const float* __restrict__ time_decay,
                                                 const float* __restrict__ time_first) {
    const int c = blockIdx.y;
    const int t = blockIdx.x * blockDim.x + threadIdx.x;
    const int b = t >> 11;
    const int d = t & (H_ - 1);
    const float w  = -__expf(time_decay[d]);
    const float tf = time_first[d];

    float num = g_pfn[c][t], den = g_pfd[c][t], mx = g_pfm[c][t];
    size_t idx = (size_t)b * S_ * H_ + (size_t)c * TCH * H_ + d;
#pragma unroll 8
    for (int s = 0; s < TCH; ++s, idx += H_) {
        float k = __half2float(g_k[idx]);
        float v = __half2float(g_v[idx]);
        float r = __half2float(g_r[idx]);

        float ktf = k + tf;
        float mo  = fmaxf(mx, ktf);
        float e1  = __expf(mx - mo);
        float e2  = __expf(ktf - mo);
        float out = __fdividef(e1 * num + e2 * v, e1 * den + e2);
        g_y[idx] = __float2half_rn(r * out);

        float mw  = mx + w;
        float mn  = fmaxf(mw, k);
        float e1n = __expf(mw - mn);
        float e2n = __expf(k - mn);
        num = e1n * num + e2n * v;
        den = e1n * den + e2n;
        mx  = mn;
    }
}

// ============================================================================
// Launch: R15 two-stream structure (best measured).
// ============================================================================
extern "C" void kernel_launch(void* const* d_in, const int* in_sizes, int n_in,
                              void* d_out, int out_size) {
    const float* hidden     = (const float*)d_in[0];
    const float* time_decay = (const float*)d_in[1];
    const float* time_first = (const float*)d_in[2];
    const float* tmk        = (const float*)d_in[3];
    const float* tmv        = (const float*)d_in[4];
    const float* tmr        = (const float*)d_in[5];
    const float* Wk         = (const float*)d_in[6];
    const float* Wv         = (const float*)d_in[7];
    const float* Wr         = (const float*)d_in[8];
    const float* Wo         = (const float*)d_in[9];
    float* out              = (float*)d_out;

    const int shm = NST * STGB;   // 144 KB

    static cudaStream_t s2 = nullptr;
    static cudaEvent_t ePrep = nullptr, eKv = nullptr, eR = nullptr;
    if (s2 == nullptr) {
        cudaFuncSetAttribute(gemm_kv,  cudaFuncAttributeMaxDynamicSharedMemorySize, shm);
        cudaFuncSetAttribute(gemm_r,   cudaFuncAttributeMaxDynamicSharedMemorySize, shm);
        cudaFuncSetAttribute(gemm_out, cudaFuncAttributeMaxDynamicSharedMemorySize, shm);
        cudaStreamCreateWithFlags(&s2, cudaStreamNonBlocking);
        cudaEventCreateWithFlags(&ePrep, cudaEventDisableTiming);
        cudaEventCreateWithFlags(&eKv,   cudaEventDisableTiming);
        cudaEventCreateWithFlags(&eR,    cudaEventDisableTiming);
    }

    // main: prep (mix + W0/W1)
    prep_kernel<<<MIX_BLOCKS + 2 * CONV_BLOCKS_PER_W, 256>>>(
        hidden, tmk, tmv, tmr, Wk, Wv);
    cudaEventRecord(ePrep, 0);

    // s2: convW23 overlapping gemm_kv
    cudaStreamWaitEvent(s2, ePrep, 0);
    convw23<<<2 * CONV_BLOCKS_PER_W, 256, 0, s2>>>(Wr, Wo);

    // main: k,v GEMMs
    dim3 gkv(N_ / 128, M_ / 256, 2);     // (16, 32, 2)
    gemm_kv<<<gkv, 512, shm>>>();
    cudaEventRecord(eKv, 0);

    // s2: r GEMM after kv (overlaps wkv pass1/pass2)
    cudaStreamWaitEvent(s2, eKv, 0);
    dim3 gfull(N_ / 128, M_ / 256);      // (16, 32)
    gemm_r<<<gfull, 512, shm, s2>>>();
    cudaEventRecord(eR, s2);

    // main: wkv pass1 + pass2
    dim3 gp(CH_ / 256, NCH);
    wkv_pass1<<<gp, 256>>>(time_decay);
    wkv_pass2<<<CH_ / 256, 256>>>(time_decay);

    // join: pass3 needs g_r
    cudaStreamWaitEvent(0, eR, 0);
    wkv_pass3<<<gp, 256>>>(time_decay, time_first);

    // main: output GEMM
    gemm_out<<<gfull, 512, shm>>>(out);
}